// round 17
// baseline (speedup 1.0000x reference)
#include <cuda_runtime.h>
#include <cstdint>

#define N_AGENTS 8192
#define G        128
#define NC       (G * G)                 // 16384 cells
#define LO       (-6.0f)
#define HVAL     (12.0f / (float)G)      // 0.09375
#define INV_H    ((float)G / 12.0f)

__device__ int    d_count[NC];
__device__ int    d_start[NC + 1];
__device__ int    d_cursor[NC];
__device__ int    d_cellOf[N_AGENTS];
__device__ float4 d_sorted[N_AGENTS];    // (gx, gy, idx-bits, 0)

__device__ __forceinline__ int cell_coord(float v) {
    int c = (int)floorf((v - LO) * INV_H);
    return min(max(c, 0), G - 1);
}

__global__ void __launch_bounds__(256) zero_kernel() {
    int i = blockIdx.x * blockDim.x + threadIdx.x;
    if (i < NC) d_count[i] = 0;
}

__global__ void __launch_bounds__(256) hist_kernel(const float* __restrict__ x) {
    int g = blockIdx.x * blockDim.x + threadIdx.x;
    if (g < N_AGENTS) {
        const float* gb = x + 3 * N_AGENTS;
        int c = cell_coord(gb[3 * g + 1]) * G + cell_coord(gb[3 * g]);
        d_cellOf[g] = c;
        atomicAdd(&d_count[c], 1);
    }
}

__global__ void __launch_bounds__(1024) scan_kernel() {
    __shared__ int ssum[1024];
    const int t = threadIdx.x;
    const int PER = NC / 1024;           // 16
    int local[PER];
    int base = t * PER, sum = 0;
    #pragma unroll
    for (int i = 0; i < PER; i++) { local[i] = sum; sum += d_count[base + i]; }
    ssum[t] = sum;
    __syncthreads();
    for (int off = 1; off < 1024; off <<= 1) {     // Hillis-Steele inclusive
        int v = (t >= off) ? ssum[t - off] : 0;
        __syncthreads();
        ssum[t] += v;
        __syncthreads();
    }
    int prev = (t == 0) ? 0 : ssum[t - 1];
    #pragma unroll
    for (int i = 0; i < PER; i++) {
        int st = prev + local[i];
        d_start[base + i]  = st;
        d_cursor[base + i] = st;
    }
    if (t == 1023) d_start[NC] = ssum[1023];
}

__global__ void __launch_bounds__(256) scatter_kernel(const float* __restrict__ x) {
    int g = blockIdx.x * blockDim.x + threadIdx.x;
    if (g < N_AGENTS) {
        const float* gb = x + 3 * N_AGENTS;
        int p = atomicAdd(&d_cursor[d_cellOf[g]], 1);
        d_sorted[p] = make_float4(gb[3 * g], gb[3 * g + 1],
                                  __int_as_float(g), 0.0f);
    }
}

__global__ void __launch_bounds__(256)
search_kernel(const float* __restrict__ x,
              const float* __restrict__ u,
              float* __restrict__ out)
{
    const int warp = (blockIdx.x * blockDim.x + threadIdx.x) >> 5;
    const int lane = threadIdx.x & 31;
    if (warp >= N_AGENTS) return;

    const float ax = x[3 * warp];
    const float ay = x[3 * warp + 1];
    const int cx = cell_coord(ax);
    const int cy = cell_coord(ay);

    const float INF = __int_as_float(0x7f800000);
    float b  = INF;
    int   bi = 0x7fffffff;

    int k = 1;
    for (;;) {
        const int ix0 = max(cx - k, 0), ix1 = min(cx + k, G - 1);
        const int iy0 = max(cy - k, 0), iy1 = min(cy + k, G - 1);

        // Rows of the box are contiguous cell runs -> contiguous goal runs.
        for (int iy = iy0; iy <= iy1; iy++) {
            const int s = d_start[iy * G + ix0];
            const int e = d_start[iy * G + ix1 + 1];
            for (int t = s + lane; t < e; t += 32) {
                float4 gv = d_sorted[t];
                float  d  = fabsf(ax - gv.x) + fabsf(ay - gv.y);
                int    gi = __float_as_int(gv.z);
                if (d < b || (d == b && gi < bi)) { b = d; bi = gi; }
            }
        }

        // Warp lexicographic (dist, idx) reduction; all lanes get the min.
        #pragma unroll
        for (int off = 16; off; off >>= 1) {
            float od = __shfl_xor_sync(0xffffffffu, b,  off);
            int   oi = __shfl_xor_sync(0xffffffffu, bi, off);
            if (od < b || (od == b && oi < bi)) { b = od; bi = oi; }
        }

        const bool full = (ix0 == 0 && ix1 == G - 1 && iy0 == 0 && iy1 == G - 1);
        if (full) break;
        // Margin: any unexamined goal's binned index is outside the box in
        // some axis => its coordinate lies beyond that boundary (clamped
        // edges => infinite margin). 1e-4 absolute slack covers all fp ulps.
        float mx0 = (ix0 == 0)     ? INF : ax - (LO + (float)ix0 * HVAL);
        float mx1 = (ix1 == G - 1) ? INF : (LO + (float)(ix1 + 1) * HVAL) - ax;
        float my0 = (iy0 == 0)     ? INF : ay - (LO + (float)iy0 * HVAL);
        float my1 = (iy1 == G - 1) ? INF : (LO + (float)(iy1 + 1) * HVAL) - ay;
        float margin = fminf(fminf(mx0, mx1), fminf(my0, my1));
        if (b + 1e-4f < margin) break;
        k <<= 1;
    }

    if (lane == 0) {
        const float* gb = x + 3 * N_AGENTS;
        float dx = gb[3 * bi]     - ax;
        float dy = gb[3 * bi + 1] - ay;

        // probs = [dx>0, dx<0, dy>0, dy<0, (dx==0)&(dy==0)]; cdf = cumsum
        float c0 = (dx > 0.0f) ? 1.0f : 0.0f;
        float c1 = c0 + ((dx < 0.0f) ? 1.0f : 0.0f);
        float c2 = c1 + ((dy > 0.0f) ? 1.0f : 0.0f);
        float c3 = c2 + ((dy < 0.0f) ? 1.0f : 0.0f);
        float c4 = c3 + ((dx == 0.0f && dy == 0.0f) ? 1.0f : 0.0f);

        float t = u[warp] * c4;

        int act = 4;
        if      (c0 >= t) act = 0;
        else if (c1 >= t) act = 1;
        else if (c2 >= t) act = 2;
        else if (c3 >= t) act = 3;

        out[warp] = (float)act;      // output dtype is float32
    }
}

extern "C" void kernel_launch(void* const* d_in, const int* in_sizes, int n_in,
                              void* d_out, int out_size)
{
    // Size-driven binding (element counts): x = 6*N, u = N.
    const float* x = nullptr;
    const float* u = nullptr;
    for (int i = 0; i < n_in; i++) {
        if (in_sizes[i] == 6 * N_AGENTS)      x = (const float*)d_in[i];
        else if (in_sizes[i] == N_AGENTS)     u = (const float*)d_in[i];
    }
    if (!x) x = (const float*)d_in[0];
    if (!u) u = (const float*)d_in[n_in > 1 ? 1 : 0];

    float* out = (float*)d_out;

    zero_kernel   <<<NC / 256, 256>>>();
    hist_kernel   <<<N_AGENTS / 256, 256>>>(x);
    scan_kernel   <<<1, 1024>>>();
    scatter_kernel<<<N_AGENTS / 256, 256>>>(x);
    search_kernel <<<(N_AGENTS * 32) / 256, 256>>>(x, u, out);
    (void)out_size;
}